// round 14
// baseline (speedup 1.0000x reference)
#include <cuda_runtime.h>
#include <cstdint>

#define NN 50000
#define EE 800000
#define KIN 256
#define HD  256
#define NH  4

// ---------------- static scratch (no runtime allocation) ----------------
__device__ float g_feat0[(size_t)NN * HD];
__device__ float g_feat1[(size_t)NN * HD];
__device__ float g_o0[(size_t)NN * HD];
__device__ float g_o1[(size_t)NN * HD];
__device__ float g_el[2][NN * NH];
__device__ float g_er[2][NN * NH];
__device__ float g_bfceff[HD];
__device__ int   g_deg[2][NN];
__device__ int   g_rowptr[2][NN + 1];
__device__ int   g_cur[2][NN];
__device__ int   g_csrc[2][EE];

// ---------------- helpers ----------------
__device__ __forceinline__ float tf32r(float x) {
    uint32_t r; asm("cvt.rna.tf32.f32 %0, %1;" : "=r"(r) : "f"(x));
    return __uint_as_float(r);
}
__device__ __forceinline__ void mma8(float& c0, float& c1, float& c2, float& c3,
                                     float a0, float a1, float a2, float a3,
                                     float b0, float b1) {
    asm volatile(
        "mma.sync.aligned.m16n8k8.row.col.f32.tf32.tf32.f32 "
        "{%0,%1,%2,%3}, {%4,%5,%6,%7}, {%8,%9}, {%0,%1,%2,%3};"
        : "+f"(c0), "+f"(c1), "+f"(c2), "+f"(c3)
        : "r"(__float_as_uint(a0)), "r"(__float_as_uint(a1)),
          "r"(__float_as_uint(a2)), "r"(__float_as_uint(a3)),
          "r"(__float_as_uint(b0)), "r"(__float_as_uint(b1)));
}
__device__ __forceinline__ float lrelu(float x) { return x > 0.0f ? x : 0.2f * x; }
__device__ __forceinline__ float pick4(float4 v, int h) {
    float ab = (h == 0) ? v.x : v.y;
    float cd = (h == 2) ? v.z : v.w;
    return (h < 2) ? ab : cd;
}

// Fragment smem geometry:
// A frags: fa = (k8*2 + rh)*10 + (wr*2 + mt)   [rh-slot stride 10 keeps write banks disjoint]
// B frags: fb = (k8*2 + wc)*8  + nt
// each frag: 32 lanes x float2, stride 66 floats (2 pad)
#define FSTR 66
#define AF_SZ (38 * FSTR)
#define BF_SZ (32 * FSTR)

// write one 16-k chunk of fragments (caller-provided role indices)
__device__ __forceinline__ void write_frags(float* frag, const float4* sv,
                                            int slotBase0, int slotBase1, int slotStride10,
                                            int w_g) {
    // slotBase0/1: frag index for k8=0/1 (already includes rh/wc and m/n tile components)
    float va[16];
#pragma unroll
    for (int i = 0; i < 4; i++) {
        va[i * 4 + 0] = sv[i].x; va[i * 4 + 1] = sv[i].y;
        va[i * 4 + 2] = sv[i].z; va[i * 4 + 3] = sv[i].w;
    }
#pragma unroll
    for (int k8 = 0; k8 < 2; k8++) {
        int f = (k8 ? slotBase1 : slotBase0);
#pragma unroll
        for (int t = 0; t < 4; t++) {
            float* p = frag + f * FSTR + (w_g * 4 + t) * 2;
            p[0] = tf32r(va[k8 * 8 + t]);
            p[1] = tf32r(va[k8 * 8 + t + 4]);
        }
    }
    (void)slotStride10;
}

// ================= GEMM1: feat_r = h @ Wg_r^T, fused el/er =================
// 256 threads, 8 warps (wr 0-3 x wc 0-1), warp tile 32x64, CTA tile 128x128.
__global__ void __launch_bounds__(256, 2) k_gemm1(
    const float* __restrict__ h,
    const float* __restrict__ Wg1, const float* __restrict__ Wg2,
    const float* __restrict__ al1, const float* __restrict__ arr1,
    const float* __restrict__ al2, const float* __restrict__ arr2)
{
    __shared__ __align__(16) float AF[AF_SZ];
    __shared__ __align__(16) float BF[BF_SZ];
    const int tid = threadIdx.x;
    const int bx = blockIdx.x, by = blockIdx.y;
    const int rel = bx >> 1;
    const int nbase = (bx & 1) * 128;
    const float* Bmat = rel ? Wg2 : Wg1;

    const int lane = tid & 31, warp = tid >> 5;
    const int wr = warp >> 1, wc = warp & 1;
    const int g = lane >> 2, tig = lane & 3;

    const bool isA = tid < 128;
    const int lrow = isA ? tid : (tid - 128);
    const int arow = by * 128 + lrow;
    const bool valid = isA ? (arow < NN) : true;
    const float* Gptr = isA ? (h + (size_t)arow * KIN)
                            : (Bmat + (size_t)(nbase + lrow) * KIN);
    // writer frag coords
    const int w_g = lrow & 7;
    const int a_s0 = ((0 * 2 + ((lrow >> 3) & 1)) * 10) + ((lrow >> 5) * 2 + ((lrow >> 4) & 1));
    const int a_s1 = ((1 * 2 + ((lrow >> 3) & 1)) * 10) + ((lrow >> 5) * 2 + ((lrow >> 4) & 1));
    const int b_s0 = ((0 * 2 + (lrow >> 6)) * 8) + ((lrow >> 3) & 7);
    const int b_s1 = ((1 * 2 + (lrow >> 6)) * 8) + ((lrow >> 3) & 7);

    float4 sv[4];
#pragma unroll
    for (int i = 0; i < 4; i++)
        sv[i] = valid ? *(const float4*)(Gptr + i * 4) : make_float4(0.f, 0.f, 0.f, 0.f);

    float c[2][8][4];
#pragma unroll
    for (int mt = 0; mt < 2; mt++)
#pragma unroll
        for (int nt = 0; nt < 8; nt++)
#pragma unroll
            for (int q = 0; q < 4; q++) c[mt][nt][q] = 0.f;

    const int NC = KIN / 16;  // 16
    for (int ck = 0; ck < NC; ck++) {
        if (isA) write_frags(AF, sv, a_s0, a_s1, 10, w_g);
        else     write_frags(BF, sv, b_s0, b_s1, 8,  w_g);
        __syncthreads();
        if (ck + 1 < NC) {
            const float* p = Gptr + (ck + 1) * 16;
#pragma unroll
            for (int i = 0; i < 4; i++)
                sv[i] = valid ? *(const float4*)(p + i * 4) : make_float4(0.f, 0.f, 0.f, 0.f);
        }
#pragma unroll
        for (int k8 = 0; k8 < 2; k8++) {
            float2 bfv[8];
#pragma unroll
            for (int nt = 0; nt < 8; nt++)
                bfv[nt] = *(const float2*)&BF[(((k8 * 2 + wc) * 8) + nt) * FSTR + lane * 2];
#pragma unroll
            for (int mt = 0; mt < 2; mt++) {
                float2 alo = *(const float2*)&AF[(((k8 * 2 + 0) * 10) + wr * 2 + mt) * FSTR + lane * 2];
                float2 ahi = *(const float2*)&AF[(((k8 * 2 + 1) * 10) + wr * 2 + mt) * FSTR + lane * 2];
#pragma unroll
                for (int nt = 0; nt < 8; nt++)
                    mma8(c[mt][nt][0], c[mt][nt][1], c[mt][nt][2], c[mt][nt][3],
                         alo.x, ahi.x, alo.y, ahi.y, bfv[nt].x, bfv[nt].y);
            }
        }
        __syncthreads();
    }

    // ---------------- epilogue: write feat + fused el/er ----------------
    const int hloc = (bx & 1) * 2 + wc;
    const float* alp = (rel ? al2 : al1) + hloc * 64;
    const float* arp = (rel ? arr2 : arr1) + hloc * 64;
    float* feat = rel ? g_feat1 : g_feat0;

    float els[4], ers[4];
#pragma unroll
    for (int i = 0; i < 4; i++) { els[i] = 0.f; ers[i] = 0.f; }
#pragma unroll
    for (int mt = 0; mt < 2; mt++) {
#pragma unroll
        for (int nt = 0; nt < 8; nt++) {
            int d0 = nt * 8 + 2 * tig;
            float w0 = alp[d0], w1 = alp[d0 + 1];
            float v0 = arp[d0], v1 = arp[d0 + 1];
            els[mt * 2 + 0] += c[mt][nt][0] * w0 + c[mt][nt][1] * w1;
            ers[mt * 2 + 0] += c[mt][nt][0] * v0 + c[mt][nt][1] * v1;
            els[mt * 2 + 1] += c[mt][nt][2] * w0 + c[mt][nt][3] * w1;
            ers[mt * 2 + 1] += c[mt][nt][2] * v0 + c[mt][nt][3] * v1;
        }
    }
#pragma unroll
    for (int i = 0; i < 4; i++) {
#pragma unroll
        for (int s = 1; s <= 2; s <<= 1) {
            els[i] += __shfl_xor_sync(0xffffffffu, els[i], s);
            ers[i] += __shfl_xor_sync(0xffffffffu, ers[i], s);
        }
    }

#pragma unroll
    for (int mt = 0; mt < 2; mt++) {
        int r0 = by * 128 + wr * 32 + mt * 16 + g;
        int r1 = r0 + 8;
        if (r0 < NN) {
            float* fb = feat + (size_t)r0 * HD + nbase + wc * 64 + 2 * tig;
#pragma unroll
            for (int nt = 0; nt < 8; nt++)
                *(float2*)(fb + nt * 8) = make_float2(c[mt][nt][0], c[mt][nt][1]);
            if (tig == 0) {
                g_el[rel][r0 * NH + hloc] = els[mt * 2 + 0];
                g_er[rel][r0 * NH + hloc] = ers[mt * 2 + 0];
            }
        }
        if (r1 < NN) {
            float* fb = feat + (size_t)r1 * HD + nbase + wc * 64 + 2 * tig;
#pragma unroll
            for (int nt = 0; nt < 8; nt++)
                *(float2*)(fb + nt * 8) = make_float2(c[mt][nt][2], c[mt][nt][3]);
            if (tig == 0) {
                g_el[rel][r1 * NH + hloc] = els[mt * 2 + 1];
                g_er[rel][r1 * NH + hloc] = ers[mt * 2 + 1];
            }
        }
    }
}

// ================= GEMM2: out = [o0 o1] @ Wfc^T + bfc_eff =================
__global__ void __launch_bounds__(256, 2) k_gemm2(const float* __restrict__ Wfc,
                                                  float* __restrict__ C)
{
    __shared__ __align__(16) float AF[AF_SZ];
    __shared__ __align__(16) float BF[BF_SZ];
    const int tid = threadIdx.x;
    const int bx = blockIdx.x, by = blockIdx.y;
    const int nbase = bx * 128;

    const int lane = tid & 31, warp = tid >> 5;
    const int wr = warp >> 1, wc = warp & 1;
    const int g = lane >> 2, tig = lane & 3;

    const bool isA = tid < 128;
    const int lrow = isA ? tid : (tid - 128);
    const int arow = by * 128 + lrow;
    const bool valid = isA ? (arow < NN) : true;
    const float* BW = Wfc + (size_t)(nbase + lrow) * 512;

    const int w_g = lrow & 7;
    const int a_s0 = ((0 * 2 + ((lrow >> 3) & 1)) * 10) + ((lrow >> 5) * 2 + ((lrow >> 4) & 1));
    const int a_s1 = ((1 * 2 + ((lrow >> 3) & 1)) * 10) + ((lrow >> 5) * 2 + ((lrow >> 4) & 1));
    const int b_s0 = ((0 * 2 + (lrow >> 6)) * 8) + ((lrow >> 3) & 7);
    const int b_s1 = ((1 * 2 + (lrow >> 6)) * 8) + ((lrow >> 3) & 7);

    float4 sv[4];
    {
        const float* p = isA ? (g_o0 + (size_t)arow * HD) : BW;
#pragma unroll
        for (int i = 0; i < 4; i++)
            sv[i] = valid ? *(const float4*)(p + i * 4) : make_float4(0.f, 0.f, 0.f, 0.f);
    }

    float c[2][8][4];
#pragma unroll
    for (int mt = 0; mt < 2; mt++)
#pragma unroll
        for (int nt = 0; nt < 8; nt++)
#pragma unroll
            for (int q = 0; q < 4; q++) c[mt][nt][q] = 0.f;

    const int NC = 512 / 16;  // 32
    for (int ck = 0; ck < NC; ck++) {
        if (isA) write_frags(AF, sv, a_s0, a_s1, 10, w_g);
        else     write_frags(BF, sv, b_s0, b_s1, 8,  w_g);
        __syncthreads();
        if (ck + 1 < NC) {
            int k0 = (ck + 1) * 16;
            const float* p;
            if (isA) p = (k0 < HD) ? (g_o0 + (size_t)arow * HD + k0)
                                   : (g_o1 + (size_t)arow * HD + (k0 - HD));
            else     p = BW + k0;
#pragma unroll
            for (int i = 0; i < 4; i++)
                sv[i] = valid ? *(const float4*)(p + i * 4) : make_float4(0.f, 0.f, 0.f, 0.f);
        }
#pragma unroll
        for (int k8 = 0; k8 < 2; k8++) {
            float2 bfv[8];
#pragma unroll
            for (int nt = 0; nt < 8; nt++)
                bfv[nt] = *(const float2*)&BF[(((k8 * 2 + wc) * 8) + nt) * FSTR + lane * 2];
#pragma unroll
            for (int mt = 0; mt < 2; mt++) {
                float2 alo = *(const float2*)&AF[(((k8 * 2 + 0) * 10) + wr * 2 + mt) * FSTR + lane * 2];
                float2 ahi = *(const float2*)&AF[(((k8 * 2 + 1) * 10) + wr * 2 + mt) * FSTR + lane * 2];
#pragma unroll
                for (int nt = 0; nt < 8; nt++)
                    mma8(c[mt][nt][0], c[mt][nt][1], c[mt][nt][2], c[mt][nt][3],
                         alo.x, ahi.x, alo.y, ahi.y, bfv[nt].x, bfv[nt].y);
            }
        }
        __syncthreads();
    }

#pragma unroll
    for (int mt = 0; mt < 2; mt++) {
        int r0 = by * 128 + wr * 32 + mt * 16 + g;
        int r1 = r0 + 8;
        int cb = nbase + wc * 64 + 2 * tig;
        if (r0 < NN) {
            float* ob = C + (size_t)r0 * HD + cb;
#pragma unroll
            for (int nt = 0; nt < 8; nt++)
                *(float2*)(ob + nt * 8) = make_float2(c[mt][nt][0] + g_bfceff[cb + nt * 8],
                                                      c[mt][nt][1] + g_bfceff[cb + nt * 8 + 1]);
        }
        if (r1 < NN) {
            float* ob = C + (size_t)r1 * HD + cb;
#pragma unroll
            for (int nt = 0; nt < 8; nt++)
                *(float2*)(ob + nt * 8) = make_float2(c[mt][nt][2] + g_bfceff[cb + nt * 8],
                                                      c[mt][nt][3] + g_bfceff[cb + nt * 8 + 1]);
        }
    }
}

// ---------------- misc small kernels ----------------
__global__ void k_zero() {
    int t = blockIdx.x * blockDim.x + threadIdx.x;
    if (t < 2 * NN) ((int*)g_deg)[t] = 0;
}

__global__ void k_bfc(const float* __restrict__ b1, const float* __restrict__ b2,
                      const float* __restrict__ Wfc, const float* __restrict__ bfc) {
    int i = threadIdx.x;
    float s = bfc[i];
    const float* w = Wfc + (size_t)i * 512;
    for (int j = 0; j < HD; j++) s += w[j] * b1[j];
    for (int j = 0; j < HD; j++) s += w[HD + j] * b2[j];
    g_bfceff[i] = s;
}

// ---------------- CSR build ----------------
__global__ void k_count(const int* __restrict__ d1, const int* __restrict__ d2) {
    int e4 = blockIdx.x * blockDim.x + threadIdx.x;
    int r = blockIdx.y;
    if (e4 >= EE / 4) return;
    const int4 v = ((const int4*)(r ? d2 : d1))[e4];
    int* deg = g_deg[r];
    atomicAdd(&deg[v.x], 1);
    atomicAdd(&deg[v.y], 1);
    atomicAdd(&deg[v.z], 1);
    atomicAdd(&deg[v.w], 1);
}

__global__ void k_scan() {
    int r = blockIdx.x;
    __shared__ int s_w[32];
    __shared__ int s_tot;
    int lane = threadIdx.x & 31, wid = threadIdx.x >> 5;
    int running = 0;
    for (int base = 0; base < NN; base += 1024) {
        int i = base + threadIdx.x;
        int v = (i < NN) ? g_deg[r][i] : 0;
        int x = v;
#pragma unroll
        for (int s = 1; s < 32; s <<= 1) {
            int y = __shfl_up_sync(0xffffffffu, x, s);
            if (lane >= s) x += y;
        }
        if (lane == 31) s_w[wid] = x;
        __syncthreads();
        if (wid == 0) {
            int t = s_w[lane];
            int xs = t;
#pragma unroll
            for (int s = 1; s < 32; s <<= 1) {
                int y = __shfl_up_sync(0xffffffffu, xs, s);
                if (lane >= s) xs += y;
            }
            s_w[lane] = xs - t;
            if (lane == 31) s_tot = xs;
        }
        __syncthreads();
        if (i < NN) {
            int v0 = running + s_w[wid] + x - v;
            g_rowptr[r][i] = v0;
            g_cur[r][i] = v0;
        }
        running += s_tot;
        __syncthreads();
    }
    if (threadIdx.x == 0) g_rowptr[r][NN] = running;
}

__global__ void k_scatter(const int* __restrict__ s1, const int* __restrict__ d1,
                          const int* __restrict__ s2, const int* __restrict__ d2) {
    int e = blockIdx.x * blockDim.x + threadIdx.x;
    int r = blockIdx.y;
    if (e >= EE) return;
    const int* S = r ? s2 : s1;
    const int* Dd = r ? d2 : d1;
    int d = Dd[e];
    int pos = atomicAdd(&g_cur[r][d], 1);
    g_csrc[r][pos] = S[e];
}

// ---------------- node-centric softmax + gather (R5 three-pass form) ----------------
__global__ void __launch_bounds__(256) k_node() {
    int gw = (blockIdx.x * 256 + threadIdx.x) >> 5;
    int lane = threadIdx.x & 31;
    int r = blockIdx.y;
    int n = gw;
    if (n >= NN) return;
    int start = g_rowptr[r][n], end = g_rowptr[r][n + 1];
    const float* el = g_el[r];
    float4 er4 = *(const float4*)(&g_er[r][n * NH]);
    const int* csrc = g_csrc[r];
    const float* feat = r ? g_feat1 : g_feat0;

    float4 m = make_float4(-3.0e38f, -3.0e38f, -3.0e38f, -3.0e38f);
    for (int i = start + lane; i < end; i += 32) {
        int s = csrc[i];
        float4 e4 = *(const float4*)(el + s * NH);
        m.x = fmaxf(m.x, lrelu(e4.x + er4.x));
        m.y = fmaxf(m.y, lrelu(e4.y + er4.y));
        m.z = fmaxf(m.z, lrelu(e4.z + er4.z));
        m.w = fmaxf(m.w, lrelu(e4.w + er4.w));
    }
#pragma unroll
    for (int s = 16; s >= 1; s >>= 1) {
        m.x = fmaxf(m.x, __shfl_xor_sync(0xffffffffu, m.x, s));
        m.y = fmaxf(m.y, __shfl_xor_sync(0xffffffffu, m.y, s));
        m.z = fmaxf(m.z, __shfl_xor_sync(0xffffffffu, m.z, s));
        m.w = fmaxf(m.w, __shfl_xor_sync(0xffffffffu, m.w, s));
    }
    float4 dn = make_float4(0.f, 0.f, 0.f, 0.f);
    for (int i = start + lane; i < end; i += 32) {
        int s = csrc[i];
        float4 e4 = *(const float4*)(el + s * NH);
        dn.x += __expf(lrelu(e4.x + er4.x) - m.x);
        dn.y += __expf(lrelu(e4.y + er4.y) - m.y);
        dn.z += __expf(lrelu(e4.z + er4.z) - m.z);
        dn.w += __expf(lrelu(e4.w + er4.w) - m.w);
    }
#pragma unroll
    for (int s = 16; s >= 1; s >>= 1) {
        dn.x += __shfl_xor_sync(0xffffffffu, dn.x, s);
        dn.y += __shfl_xor_sync(0xffffffffu, dn.y, s);
        dn.z += __shfl_xor_sync(0xffffffffu, dn.z, s);
        dn.w += __shfl_xor_sync(0xffffffffu, dn.w, s);
    }
    float4 inv = make_float4(dn.x > 0.f ? 1.f / dn.x : 0.f,
                             dn.y > 0.f ? 1.f / dn.y : 0.f,
                             dn.z > 0.f ? 1.f / dn.z : 0.f,
                             dn.w > 0.f ? 1.f / dn.w : 0.f);
    int head = lane >> 3;
    float erh = pick4(er4, head);
    float mh = pick4(m, head);
    float ih = pick4(inv, head);
    float acc[8] = {0.f, 0.f, 0.f, 0.f, 0.f, 0.f, 0.f, 0.f};
    for (int i = start; i < end; i++) {
        int s = csrc[i];
        float4 e4 = *(const float4*)(el + s * NH);
        float a = __expf(lrelu(pick4(e4, head) + erh) - mh) * ih;
        const float* f = feat + (size_t)s * HD + lane * 8;
        float4 f0 = *(const float4*)f, f1 = *(const float4*)(f + 4);
        acc[0] += a * f0.x; acc[1] += a * f0.y; acc[2] += a * f0.z; acc[3] += a * f0.w;
        acc[4] += a * f1.x; acc[5] += a * f1.y; acc[6] += a * f1.z; acc[7] += a * f1.w;
    }
    float* o = (r ? g_o1 : g_o0) + (size_t)n * HD + lane * 8;
    *(float4*)o = make_float4(acc[0], acc[1], acc[2], acc[3]);
    *(float4*)(o + 4) = make_float4(acc[4], acc[5], acc[6], acc[7]);
}

// ---------------- launch ----------------
extern "C" void kernel_launch(void* const* d_in, const int* in_sizes, int n_in,
                              void* d_out, int out_size) {
    const float* h   = (const float*)d_in[0];
    const float* Wg1 = (const float*)d_in[1];
    const float* al1 = (const float*)d_in[2];
    const float* ar1 = (const float*)d_in[3];
    const float* b1  = (const float*)d_in[4];
    const float* Wg2 = (const float*)d_in[5];
    const float* al2 = (const float*)d_in[6];
    const float* ar2 = (const float*)d_in[7];
    const float* b2  = (const float*)d_in[8];
    const float* Wfc = (const float*)d_in[9];
    const float* bfc = (const float*)d_in[10];
    const int* src1  = (const int*)d_in[11];
    const int* dst1  = (const int*)d_in[12];
    const int* src2  = (const int*)d_in[13];
    const int* dst2  = (const int*)d_in[14];
    float* out = (float*)d_out;

    // order: k_gemm1 is 4th launch (ncu capture slot)
    k_zero<<<(2 * NN + 255) / 256, 256>>>();

    dim3 gc((EE / 4 + 255) / 256, 2);
    k_count<<<gc, 256>>>(dst1, dst2);

    k_bfc<<<1, 256>>>(b1, b2, Wfc, bfc);

    dim3 g1(4, (NN + 127) / 128);
    k_gemm1<<<g1, 256>>>(h, Wg1, Wg2, al1, ar1, al2, ar2);

    k_scan<<<2, 1024>>>();

    dim3 ge((EE + 255) / 256, 2);
    k_scatter<<<ge, 256>>>(src1, dst1, src2, dst2);

    dim3 gn((NN + 7) / 8, 2);
    k_node<<<gn, 256>>>();

    dim3 g2(2, (NN + 127) / 128);
    k_gemm2<<<g2, 256>>>(Wfc, out);
}

// round 17
// speedup vs baseline: 1.1096x; 1.1096x over previous
#include <cuda_runtime.h>
#include <cuda_fp16.h>
#include <cstdint>

#define NN 50000
#define EE 800000
#define KIN 256
#define HD  256
#define NH  4

// ---------------- static scratch (no runtime allocation) ----------------
__device__ float g_feat0[(size_t)NN * HD];
__device__ float g_feat1[(size_t)NN * HD];
__device__ float g_o0[(size_t)NN * HD];
__device__ float g_o1[(size_t)NN * HD];
__device__ float g_el[2][NN * NH];
__device__ float g_er[2][NN * NH];
__device__ float g_bfceff[HD];
__device__ int   g_deg[2][NN];
__device__ int   g_rowptr[2][NN + 1];
__device__ int   g_cur[2][NN];
__device__ int   g_csrc[2][EE];

// ---------------- helpers ----------------
__device__ __forceinline__ void mma16(float& c0, float& c1, float& c2, float& c3,
                                      uint32_t a0, uint32_t a1, uint32_t a2, uint32_t a3,
                                      uint32_t b0, uint32_t b1) {
    asm volatile(
        "mma.sync.aligned.m16n8k16.row.col.f32.f16.f16.f32 "
        "{%0,%1,%2,%3}, {%4,%5,%6,%7}, {%8,%9}, {%0,%1,%2,%3};"
        : "+f"(c0), "+f"(c1), "+f"(c2), "+f"(c3)
        : "r"(a0), "r"(a1), "r"(a2), "r"(a3), "r"(b0), "r"(b1));
}
__device__ __forceinline__ float lrelu(float x) { return x > 0.0f ? x : 0.2f * x; }
__device__ __forceinline__ float pick4(float4 v, int h) {
    float ab = (h == 0) ? v.x : v.y;
    float cd = (h == 2) ? v.z : v.w;
    return (h < 2) ? ab : cd;
}

// ================= GEMM1: feat_r = h @ Wg_r^T, fused el/er =================
// 128 threads, 2x2 warps of 64x64, CTA tile 128x128, BK=16, fp16 mma m16n8k16.
// smem layout: X2[k2][row], k2 = k/2 (half2 packs k, k+1). pad 136 -> conflict-free.
__global__ void __launch_bounds__(128, 2) k_gemm1(
    const float* __restrict__ h,
    const float* __restrict__ Wg1, const float* __restrict__ Wg2,
    const float* __restrict__ al1, const float* __restrict__ arr1,
    const float* __restrict__ al2, const float* __restrict__ arr2)
{
    __shared__ __half2 As2[8][136];
    __shared__ __half2 Bs2[8][136];
    const int tid = threadIdx.x;
    const int bx = blockIdx.x, by = blockIdx.y;
    const int rel = bx >> 1;
    const int nbase = (bx & 1) * 128;
    const float* Bmat = rel ? Wg2 : Wg1;

    const int lane = tid & 31, warp = tid >> 5;
    const int wr = warp >> 1, wc = warp & 1;
    const int g = lane >> 2, tig = lane & 3;

    const int arow = by * 128 + tid;
    const bool av = arow < NN;
    const float* Aptr = h + (size_t)arow * KIN;
    const float* Bptr = Bmat + (size_t)(nbase + tid) * KIN;

    float4 sa[4], sb[4];
#pragma unroll
    for (int i = 0; i < 4; i++) {
        sa[i] = av ? *(const float4*)(Aptr + i * 4) : make_float4(0.f, 0.f, 0.f, 0.f);
        sb[i] = *(const float4*)(Bptr + i * 4);
    }

    float c[4][8][4];
#pragma unroll
    for (int mt = 0; mt < 4; mt++)
#pragma unroll
        for (int nt = 0; nt < 8; nt++)
#pragma unroll
            for (int q = 0; q < 4; q++) c[mt][nt][q] = 0.f;

    const int NC = KIN / 16;  // 16
    for (int ck = 0; ck < NC; ck++) {
#pragma unroll
        for (int i = 0; i < 4; i++) {
            As2[2 * i + 0][tid] = __floats2half2_rn(sa[i].x, sa[i].y);
            As2[2 * i + 1][tid] = __floats2half2_rn(sa[i].z, sa[i].w);
            Bs2[2 * i + 0][tid] = __floats2half2_rn(sb[i].x, sb[i].y);
            Bs2[2 * i + 1][tid] = __floats2half2_rn(sb[i].z, sb[i].w);
        }
        __syncthreads();
        if (ck + 1 < NC) {
            const float* ap = Aptr + (ck + 1) * 16;
            const float* bp = Bptr + (ck + 1) * 16;
#pragma unroll
            for (int i = 0; i < 4; i++) {
                sa[i] = av ? *(const float4*)(ap + i * 4) : make_float4(0.f, 0.f, 0.f, 0.f);
                sb[i] = *(const float4*)(bp + i * 4);
            }
        }
        {
            uint32_t bf[8][2];
#pragma unroll
            for (int nt = 0; nt < 8; nt++) {
                int col = wc * 64 + nt * 8 + g;
                bf[nt][0] = *(const uint32_t*)&Bs2[tig][col];
                bf[nt][1] = *(const uint32_t*)&Bs2[tig + 4][col];
            }
#pragma unroll
            for (int mt = 0; mt < 4; mt++) {
                int mb = wr * 64 + mt * 16 + g;
                uint32_t a0 = *(const uint32_t*)&As2[tig][mb];
                uint32_t a1 = *(const uint32_t*)&As2[tig][mb + 8];
                uint32_t a2 = *(const uint32_t*)&As2[tig + 4][mb];
                uint32_t a3 = *(const uint32_t*)&As2[tig + 4][mb + 8];
#pragma unroll
                for (int nt = 0; nt < 8; nt++)
                    mma16(c[mt][nt][0], c[mt][nt][1], c[mt][nt][2], c[mt][nt][3],
                          a0, a1, a2, a3, bf[nt][0], bf[nt][1]);
            }
        }
        __syncthreads();
    }

    // ---------------- epilogue: write feat + fused el/er ----------------
    const int hloc = (bx & 1) * 2 + wc;
    const float* alp = (rel ? al2 : al1) + hloc * 64;
    const float* arp = (rel ? arr2 : arr1) + hloc * 64;
    float* feat = rel ? g_feat1 : g_feat0;

    float els[8], ers[8];
#pragma unroll
    for (int i = 0; i < 8; i++) { els[i] = 0.f; ers[i] = 0.f; }

#pragma unroll
    for (int mt = 0; mt < 4; mt++) {
#pragma unroll
        for (int nt = 0; nt < 8; nt++) {
            int d0 = nt * 8 + 2 * tig;
            float w0 = alp[d0], w1 = alp[d0 + 1];
            float v0 = arp[d0], v1 = arp[d0 + 1];
            els[mt * 2 + 0] += c[mt][nt][0] * w0 + c[mt][nt][1] * w1;
            ers[mt * 2 + 0] += c[mt][nt][0] * v0 + c[mt][nt][1] * v1;
            els[mt * 2 + 1] += c[mt][nt][2] * w0 + c[mt][nt][3] * w1;
            ers[mt * 2 + 1] += c[mt][nt][2] * v0 + c[mt][nt][3] * v1;
        }
    }
#pragma unroll
    for (int i = 0; i < 8; i++) {
#pragma unroll
        for (int s = 1; s <= 2; s <<= 1) {
            els[i] += __shfl_xor_sync(0xffffffffu, els[i], s);
            ers[i] += __shfl_xor_sync(0xffffffffu, ers[i], s);
        }
    }

#pragma unroll
    for (int mt = 0; mt < 4; mt++) {
        int r0 = by * 128 + wr * 64 + mt * 16 + g;
        int r1 = r0 + 8;
        if (r0 < NN) {
            float* fb = feat + (size_t)r0 * HD + nbase + wc * 64 + 2 * tig;
#pragma unroll
            for (int nt = 0; nt < 8; nt++)
                *(float2*)(fb + nt * 8) = make_float2(c[mt][nt][0], c[mt][nt][1]);
            if (tig == 0) {
                g_el[rel][r0 * NH + hloc] = els[mt * 2 + 0];
                g_er[rel][r0 * NH + hloc] = ers[mt * 2 + 0];
            }
        }
        if (r1 < NN) {
            float* fb = feat + (size_t)r1 * HD + nbase + wc * 64 + 2 * tig;
#pragma unroll
            for (int nt = 0; nt < 8; nt++)
                *(float2*)(fb + nt * 8) = make_float2(c[mt][nt][2], c[mt][nt][3]);
            if (tig == 0) {
                g_el[rel][r1 * NH + hloc] = els[mt * 2 + 1];
                g_er[rel][r1 * NH + hloc] = ers[mt * 2 + 1];
            }
        }
    }
}

// ================= GEMM2: out = [o0 o1] @ Wfc^T + bfc_eff =================
__global__ void __launch_bounds__(128, 2) k_gemm2(const float* __restrict__ Wfc,
                                                  float* __restrict__ C)
{
    __shared__ __half2 As2[8][136];
    __shared__ __half2 Bs2[8][136];
    const int tid = threadIdx.x;
    const int bx = blockIdx.x, by = blockIdx.y;
    const int nbase = bx * 128;

    const int lane = tid & 31, warp = tid >> 5;
    const int wr = warp >> 1, wc = warp & 1;
    const int g = lane >> 2, tig = lane & 3;

    const int arow = by * 128 + tid;
    const bool av = arow < NN;
    const float* Bptr = Wfc + (size_t)(nbase + tid) * 512;

    float4 sa[4], sb[4];
    {
        const float* ap = g_o0 + (size_t)arow * HD;
#pragma unroll
        for (int i = 0; i < 4; i++) {
            sa[i] = av ? *(const float4*)(ap + i * 4) : make_float4(0.f, 0.f, 0.f, 0.f);
            sb[i] = *(const float4*)(Bptr + i * 4);
        }
    }

    float c[4][8][4];
#pragma unroll
    for (int mt = 0; mt < 4; mt++)
#pragma unroll
        for (int nt = 0; nt < 8; nt++)
#pragma unroll
            for (int q = 0; q < 4; q++) c[mt][nt][q] = 0.f;

    const int NC = 512 / 16;  // 32
    for (int ck = 0; ck < NC; ck++) {
#pragma unroll
        for (int i = 0; i < 4; i++) {
            As2[2 * i + 0][tid] = __floats2half2_rn(sa[i].x, sa[i].y);
            As2[2 * i + 1][tid] = __floats2half2_rn(sa[i].z, sa[i].w);
            Bs2[2 * i + 0][tid] = __floats2half2_rn(sb[i].x, sb[i].y);
            Bs2[2 * i + 1][tid] = __floats2half2_rn(sb[i].z, sb[i].w);
        }
        __syncthreads();
        if (ck + 1 < NC) {
            int k0 = (ck + 1) * 16;
            const float* ap = (k0 < HD) ? (g_o0 + (size_t)arow * HD + k0)
                                        : (g_o1 + (size_t)arow * HD + (k0 - HD));
            const float* bp = Bptr + k0;
#pragma unroll
            for (int i = 0; i < 4; i++) {
                sa[i] = av ? *(const float4*)(ap + i * 4) : make_float4(0.f, 0.f, 0.f, 0.f);
                sb[i] = *(const float4*)(bp + i * 4);
            }
        }
        {
            uint32_t bf[8][2];
#pragma unroll
            for (int nt = 0; nt < 8; nt++) {
                int col = wc * 64 + nt * 8 + g;
                bf[nt][0] = *(const uint32_t*)&Bs2[tig][col];
                bf[nt][1] = *(const uint32_t*)&Bs2[tig + 4][col];
            }
#pragma unroll
            for (int mt = 0; mt < 4; mt++) {
                int mb = wr * 64 + mt * 16 + g;
                uint32_t a0 = *(const uint32_t*)&As2[tig][mb];
                uint32_t a1 = *(const uint32_t*)&As2[tig][mb + 8];
                uint32_t a2 = *(const uint32_t*)&As2[tig + 4][mb];
                uint32_t a3 = *(const uint32_t*)&As2[tig + 4][mb + 8];
#pragma unroll
                for (int nt = 0; nt < 8; nt++)
                    mma16(c[mt][nt][0], c[mt][nt][1], c[mt][nt][2], c[mt][nt][3],
                          a0, a1, a2, a3, bf[nt][0], bf[nt][1]);
            }
        }
        __syncthreads();
    }

#pragma unroll
    for (int mt = 0; mt < 4; mt++) {
        int r0 = by * 128 + wr * 64 + mt * 16 + g;
        int r1 = r0 + 8;
        int cb = nbase + wc * 64 + 2 * tig;
        if (r0 < NN) {
            float* ob = C + (size_t)r0 * HD + cb;
#pragma unroll
            for (int nt = 0; nt < 8; nt++)
                *(float2*)(ob + nt * 8) = make_float2(c[mt][nt][0] + g_bfceff[cb + nt * 8],
                                                      c[mt][nt][1] + g_bfceff[cb + nt * 8 + 1]);
        }
        if (r1 < NN) {
            float* ob = C + (size_t)r1 * HD + cb;
#pragma unroll
            for (int nt = 0; nt < 8; nt++)
                *(float2*)(ob + nt * 8) = make_float2(c[mt][nt][2] + g_bfceff[cb + nt * 8],
                                                      c[mt][nt][3] + g_bfceff[cb + nt * 8 + 1]);
        }
    }
}

// ---------------- misc small kernels ----------------
__global__ void k_zero() {
    int t = blockIdx.x * blockDim.x + threadIdx.x;
    if (t < 2 * NN) ((int*)g_deg)[t] = 0;
}

__global__ void k_bfc(const float* __restrict__ b1, const float* __restrict__ b2,
                      const float* __restrict__ Wfc, const float* __restrict__ bfc) {
    int i = threadIdx.x;
    float s = bfc[i];
    const float* w = Wfc + (size_t)i * 512;
    for (int j = 0; j < HD; j++) s += w[j] * b1[j];
    for (int j = 0; j < HD; j++) s += w[HD + j] * b2[j];
    g_bfceff[i] = s;
}

// ---------------- CSR build ----------------
__global__ void k_count(const int* __restrict__ d1, const int* __restrict__ d2) {
    int e4 = blockIdx.x * blockDim.x + threadIdx.x;
    int r = blockIdx.y;
    if (e4 >= EE / 4) return;
    const int4 v = ((const int4*)(r ? d2 : d1))[e4];
    int* deg = g_deg[r];
    atomicAdd(&deg[v.x], 1);
    atomicAdd(&deg[v.y], 1);
    atomicAdd(&deg[v.z], 1);
    atomicAdd(&deg[v.w], 1);
}

__global__ void k_scan() {
    int r = blockIdx.x;
    __shared__ int s_w[32];
    __shared__ int s_tot;
    int lane = threadIdx.x & 31, wid = threadIdx.x >> 5;
    int running = 0;
    for (int base = 0; base < NN; base += 1024) {
        int i = base + threadIdx.x;
        int v = (i < NN) ? g_deg[r][i] : 0;
        int x = v;
#pragma unroll
        for (int s = 1; s < 32; s <<= 1) {
            int y = __shfl_up_sync(0xffffffffu, x, s);
            if (lane >= s) x += y;
        }
        if (lane == 31) s_w[wid] = x;
        __syncthreads();
        if (wid == 0) {
            int t = s_w[lane];
            int xs = t;
#pragma unroll
            for (int s = 1; s < 32; s <<= 1) {
                int y = __shfl_up_sync(0xffffffffu, xs, s);
                if (lane >= s) xs += y;
            }
            s_w[lane] = xs - t;
            if (lane == 31) s_tot = xs;
        }
        __syncthreads();
        if (i < NN) {
            int v0 = running + s_w[wid] + x - v;
            g_rowptr[r][i] = v0;
            g_cur[r][i] = v0;
        }
        running += s_tot;
        __syncthreads();
    }
    if (threadIdx.x == 0) g_rowptr[r][NN] = running;
}

__global__ void k_scatter(const int* __restrict__ s1, const int* __restrict__ d1,
                          const int* __restrict__ s2, const int* __restrict__ d2) {
    int e = blockIdx.x * blockDim.x + threadIdx.x;
    int r = blockIdx.y;
    if (e >= EE) return;
    const int* S = r ? s2 : s1;
    const int* Dd = r ? d2 : d1;
    int d = Dd[e];
    int pos = atomicAdd(&g_cur[r][d], 1);
    g_csrc[r][pos] = S[e];
}

// ---------------- node-centric softmax + gather (R5 three-pass form) ----------------
__global__ void __launch_bounds__(256) k_node() {
    int gw = (blockIdx.x * 256 + threadIdx.x) >> 5;
    int lane = threadIdx.x & 31;
    int r = blockIdx.y;
    int n = gw;
    if (n >= NN) return;
    int start = g_rowptr[r][n], end = g_rowptr[r][n + 1];
    const float* el = g_el[r];
    float4 er4 = *(const float4*)(&g_er[r][n * NH]);
    const int* csrc = g_csrc[r];
    const float* feat = r ? g_feat1 : g_feat0;

    float4 m = make_float4(-3.0e38f, -3.0e38f, -3.0e38f, -3.0e38f);
    for (int i = start + lane; i < end; i += 32) {
        int s = csrc[i];
        float4 e4 = *(const float4*)(el + s * NH);
        m.x = fmaxf(m.x, lrelu(e4.x + er4.x));
        m.y = fmaxf(m.y, lrelu(e4.y + er4.y));
        m.z = fmaxf(m.z, lrelu(e4.z + er4.z));
        m.w = fmaxf(m.w, lrelu(e4.w + er4.w));
    }
#pragma unroll
    for (int s = 16; s >= 1; s >>= 1) {
        m.x = fmaxf(m.x, __shfl_xor_sync(0xffffffffu, m.x, s));
        m.y = fmaxf(m.y, __shfl_xor_sync(0xffffffffu, m.y, s));
        m.z = fmaxf(m.z, __shfl_xor_sync(0xffffffffu, m.z, s));
        m.w = fmaxf(m.w, __shfl_xor_sync(0xffffffffu, m.w, s));
    }
    float4 dn = make_float4(0.f, 0.f, 0.f, 0.f);
    for (int i = start + lane; i < end; i += 32) {
        int s = csrc[i];
        float4 e4 = *(const float4*)(el + s * NH);
        dn.x += __expf(lrelu(e4.x + er4.x) - m.x);
        dn.y += __expf(lrelu(e4.y + er4.y) - m.y);
        dn.z += __expf(lrelu(e4.z + er4.z) - m.z);
        dn.w += __expf(lrelu(e4.w + er4.w) - m.w);
    }
#pragma unroll
    for (int s = 16; s >= 1; s >>= 1) {
        dn.x += __shfl_xor_sync(0xffffffffu, dn.x, s);
        dn.y += __shfl_xor_sync(0xffffffffu, dn.y, s);
        dn.z += __shfl_xor_sync(0xffffffffu, dn.z, s);
        dn.w += __shfl_xor_sync(0xffffffffu, dn.w, s);
    }
    float4 inv = make_float4(dn.x > 0.f ? 1.f / dn.x : 0.f,
                             dn.y > 0.f ? 1.f / dn.y : 0.f,
                             dn.z > 0.f ? 1.f / dn.z : 0.f,
                             dn.w > 0.f ? 1.f / dn.w : 0.f);
    int head = lane >> 3;
    float erh = pick4(er4, head);
    float mh = pick4(m, head);
    float ih = pick4(inv, head);
    float acc[8] = {0.f, 0.f, 0.f, 0.f, 0.f, 0.f, 0.f, 0.f};
    for (int i = start; i < end; i++) {
        int s = csrc[i];
        float4 e4 = *(const float4*)(el + s * NH);
        float a = __expf(lrelu(pick4(e4, head) + erh) - mh) * ih;
        const float* f = feat + (size_t)s * HD + lane * 8;
        float4 f0 = *(const float4*)f, f1 = *(const float4*)(f + 4);
        acc[0] += a * f0.x; acc[1] += a * f0.y; acc[2] += a * f0.z; acc[3] += a * f0.w;
        acc[4] += a * f1.x; acc[5] += a * f1.y; acc[6] += a * f1.z; acc[7] += a * f1.w;
    }
    float* o = (r ? g_o1 : g_o0) + (size_t)n * HD + lane * 8;
    *(float4*)o = make_float4(acc[0], acc[1], acc[2], acc[3]);
    *(float4*)(o + 4) = make_float4(acc[4], acc[5], acc[6], acc[7]);
}

// ---------------- launch ----------------
extern "C" void kernel_launch(void* const* d_in, const int* in_sizes, int n_in,
                              void* d_out, int out_size) {
    const float* h   = (const float*)d_in[0];
    const float* Wg1 = (const float*)d_in[1];
    const float* al1 = (const float*)d_in[2];
    const float* ar1 = (const float*)d_in[3];
    const float* b1  = (const float*)d_in[4];
    const float* Wg2 = (const float*)d_in[5];
    const float* al2 = (const float*)d_in[6];
    const float* ar2 = (const float*)d_in[7];
    const float* b2  = (const float*)d_in[8];
    const float* Wfc = (const float*)d_in[9];
    const float* bfc = (const float*)d_in[10];
    const int* src1  = (const int*)d_in[11];
    const int* dst1  = (const int*)d_in[12];
    const int* src2  = (const int*)d_in[13];
    const int* dst2  = (const int*)d_in[14];
    float* out = (float*)d_out;

    // order: k_gemm1 is 4th launch (ncu capture slot)
    k_zero<<<(2 * NN + 255) / 256, 256>>>();

    dim3 gc((EE / 4 + 255) / 256, 2);
    k_count<<<gc, 256>>>(dst1, dst2);

    k_bfc<<<1, 256>>>(b1, b2, Wfc, bfc);

    dim3 g1(4, (NN + 127) / 128);
    k_gemm1<<<g1, 128>>>(h, Wg1, Wg2, al1, ar1, al2, ar2);

    k_scan<<<2, 1024>>>();

    dim3 ge((EE + 255) / 256, 2);
    k_scatter<<<ge, 256>>>(src1, dst1, src2, dst2);

    dim3 gn((NN + 7) / 8, 2);
    k_node<<<gn, 256>>>();

    dim3 g2(2, (NN + 127) / 128);
    k_gemm2<<<g2, 128>>>(Wfc, out);
}